// round 5
// baseline (speedup 1.0000x reference)
#include <cuda_runtime.h>
#include <math.h>

// Problem constants
#define NN 16
#define CC 256
#define HH 96
#define WW 96
#define HW (HH*WW)          // 9216
#define RED 16
#define HID (CC/RED)        // 16
#define KK 3
#define DYN (CC*KK*KK)      // 2304
#define EPS 1e-5f

// Scratch (allocation-free rule: __device__ globals)
__device__ float d_g[NN*CC];      // sigmoid gate per (n,c)
__device__ float d_gap[NN*CC];    // g * mean  (== mean of srm)
__device__ float d_filt[NN*DYN];  // g-folded dynamic 3x3 filters

// ---------------------------------------------------------------------------
// Kernel 1: per-(n,c) mean/std -> gate g, gap = g*mean
// grid = N*C blocks, 256 threads
// ---------------------------------------------------------------------------
__global__ void __launch_bounds__(256) stats_kernel(const float* __restrict__ x,
                                                    const float* __restrict__ cfc) {
    int nc = blockIdx.x;
    const float4* xp = (const float4*)(x + (size_t)nc * HW);

    float s = 0.f, s2 = 0.f;
    #pragma unroll
    for (int i = threadIdx.x; i < HW/4; i += 256) {
        float4 v = xp[i];
        s  += v.x + v.y + v.z + v.w;
        s2 += v.x*v.x + v.y*v.y + v.z*v.z + v.w*v.w;
    }
    // warp reduce
    #pragma unroll
    for (int o = 16; o; o >>= 1) {
        s  += __shfl_xor_sync(0xffffffffu, s,  o);
        s2 += __shfl_xor_sync(0xffffffffu, s2, o);
    }
    __shared__ float ss[8], ss2[8];
    int w = threadIdx.x >> 5;
    if ((threadIdx.x & 31) == 0) { ss[w] = s; ss2[w] = s2; }
    __syncthreads();
    if (threadIdx.x == 0) {
        s = 0.f; s2 = 0.f;
        #pragma unroll
        for (int i = 0; i < 8; i++) { s += ss[i]; s2 += ss2[i]; }
        float mean = s * (1.f / (float)HW);
        float var  = (s2 - s * mean) * (1.f / (float)(HW - 1));  // unbiased
        float stdv = sqrtf(var + EPS);
        int c = nc & (CC - 1);
        float z = mean * cfc[2*c] + stdv * cfc[2*c + 1];
        float g = 1.f / (1.f + __expf(-z));
        d_g[nc]   = g;
        d_gap[nc] = g * mean;
    }
}

// ---------------------------------------------------------------------------
// Kernel 2: tiny MLP -> dynamic filters (g folded in)
// grid = N blocks, 256 threads
// ---------------------------------------------------------------------------
__global__ void __launch_bounds__(256) mlp_kernel(const float* __restrict__ w1,
                                                  const float* __restrict__ b1,
                                                  const float* __restrict__ w2,
                                                  const float* __restrict__ b2) {
    int n = blockIdx.x;
    __shared__ float gap_s[CC];
    __shared__ float hid_s[HID];

    gap_s[threadIdx.x] = d_gap[n*CC + threadIdx.x];
    __syncthreads();

    // hid[r] = relu(b1[r] + sum_c gap[c]*w1[r,c]); 16 groups of 16 threads
    {
        int r = threadIdx.x >> 4;       // 0..15
        int p = threadIdx.x & 15;       // 0..15
        const float* wr = w1 + r * CC;
        float acc = 0.f;
        #pragma unroll
        for (int c = p; c < CC; c += 16) acc += gap_s[c] * wr[c];
        // reduce 16 partials within half-warp via shuffle
        #pragma unroll
        for (int o = 8; o; o >>= 1) acc += __shfl_xor_sync(0xffffffffu, acc, o);
        if (p == 0) hid_s[r] = fmaxf(acc + b1[r], 0.f);
    }
    __syncthreads();

    // dyn[o] = b2[o] + sum_r hid[r]*w2[o,r];  filt = g * dyn
    for (int o = threadIdx.x; o < DYN; o += 256) {
        const float* wr = w2 + o * HID;
        float acc = b2[o];
        #pragma unroll
        for (int r = 0; r < HID; r++) acc += hid_s[r] * wr[r];
        int c = o / (KK*KK);
        d_filt[n*DYN + o] = acc * d_g[n*CC + c];
    }
}

// ---------------------------------------------------------------------------
// Kernel 3: depthwise 3x3 conv, zero pad, per-(n,c) dynamic filter
// grid = N*C blocks, blockDim (96,4) = 384 threads
// smem tile: (96+2) x (96+2) padded image
// ---------------------------------------------------------------------------
#define SW 98
__global__ void __launch_bounds__(384) conv_kernel(const float* __restrict__ x,
                                                   float* __restrict__ out) {
    __shared__ float tile[SW*SW];   // 38416 B
    __shared__ float fs[9];

    int nc = blockIdx.x;
    const float* xin = x + (size_t)nc * HW;
    int t = threadIdx.x + WW * threadIdx.y;   // 0..383

    if (t < 9) fs[t] = d_filt[nc*9 + t];

    // zero halo: 388 elements, strided so ALL are covered by 384 threads
    // (one-shot version left cells 384..387 stale -> 1e-2 rel_err)
    for (int i = t; i < 2*SW + 2*HH; i += 384) {       // 388 total
        if (i < SW)            tile[i] = 0.f;                        // top row
        else if (i < 2*SW)     tile[97*SW + (i - SW)] = 0.f;         // bottom row
        else if (i < 2*SW+HH)  tile[(i - 2*SW + 1)*SW + 0]  = 0.f;   // left col
        else                   tile[(i - 2*SW - HH + 1)*SW + 97] = 0.f; // right col
    }

    // load interior, vectorized: 2304 float4, 6 per thread
    const float4* xp = (const float4*)xin;
    #pragma unroll
    for (int i = t; i < HW/4; i += 384) {
        float4 v = xp[i];
        int e = i * 4;
        int h = e / WW, c = e - h * WW;
        float* dst = &tile[(h+1)*SW + (c+1)];
        dst[0] = v.x; dst[1] = v.y; dst[2] = v.z; dst[3] = v.w;
    }
    __syncthreads();

    float f0 = fs[0], f1 = fs[1], f2 = fs[2];
    float f3 = fs[3], f4 = fs[4], f5 = fs[5];
    float f6 = fs[6], f7 = fs[7], f8 = fs[8];

    int w  = threadIdx.x;                 // output column 0..95
    int h0 = threadIdx.y * (HH/4);        // 24-row strip
    const float* r = &tile[h0*SW + w];    // smem row (h0-1)+1, col (w-1)+1
    float* op = out + (size_t)nc * HW + h0 * WW + w;

    float a0 = r[0], a1 = r[1], a2 = r[2]; r += SW;
    float b0 = r[0], b1 = r[1], b2 = r[2];

    #pragma unroll
    for (int i = 0; i < HH/4; i++) {
        r += SW;
        float c0 = r[0], c1 = r[1], c2 = r[2];
        float acc = f0*a0 + f1*a1 + f2*a2
                  + f3*b0 + f4*b1 + f5*b2
                  + f6*c0 + f7*c1 + f8*c2;
        op[i * WW] = acc;
        a0 = b0; a1 = b1; a2 = b2;
        b0 = c0; b1 = c1; b2 = c2;
    }
}

// ---------------------------------------------------------------------------
extern "C" void kernel_launch(void* const* d_in, const int* in_sizes, int n_in,
                              void* d_out, int out_size) {
    const float* x   = (const float*)d_in[0];
    const float* cfc = (const float*)d_in[1];
    const float* w1  = (const float*)d_in[2];
    const float* b1  = (const float*)d_in[3];
    const float* w2  = (const float*)d_in[4];
    const float* b2  = (const float*)d_in[5];
    float* out = (float*)d_out;

    stats_kernel<<<NN*CC, 256>>>(x, cfc);
    mlp_kernel<<<NN, 256>>>(w1, b1, w2, b2);
    conv_kernel<<<NN*CC, dim3(WW, 4)>>>(x, out);
}